// round 2
// baseline (speedup 1.0000x reference)
#include <cuda_runtime.h>
#include <cstdint>

#define T_ 512
#define H_ 2048
#define F_ 768
#define E_ 64
#define K_ 8
#define KC 16   // K-chunk per pipeline stage

// ---------------- scratch (static __device__, allocation-free) ----------------
__device__ int   g_cnt[E_];
__device__ int   g_off[E_];
__device__ int   g_tok[E_][T_];
__device__ float g_cw [E_][T_];
__device__ float g_h  [(size_t)T_ * K_ * F_];   // 12.6 MB, compact (scan offsets)

// ---------------- helpers ----------------
__device__ __forceinline__ unsigned f2tf(float f) {
    unsigned r; asm("cvt.rna.tf32.f32 %0, %1;" : "=r"(r) : "f"(f)); return r;
}
__device__ __forceinline__ void mma_tf32(float c[4],
    unsigned a0, unsigned a1, unsigned a2, unsigned a3,
    unsigned b0, unsigned b1) {
    asm volatile(
        "mma.sync.aligned.m16n8k8.row.col.f32.tf32.tf32.f32 "
        "{%0,%1,%2,%3}, {%4,%5,%6,%7}, {%8,%9}, {%0,%1,%2,%3};\n"
        : "+f"(c[0]), "+f"(c[1]), "+f"(c[2]), "+f"(c[3])
        : "r"(a0), "r"(a1), "r"(a2), "r"(a3), "r"(b0), "r"(b1));
}
// Split fp32 v into tf32 hi + tf32 lo (Dekker): v ≈ hi + lo, |err| ~ 2^-22 |v|
__device__ __forceinline__ void tfsplit(float v, unsigned& hi, unsigned& lo) {
    hi = f2tf(v);
    lo = f2tf(v - __uint_as_float(hi));
}

// ---------------- kernel 0: zero output + counters ----------------
__global__ void k_zero(float* __restrict__ out) {
    int i = blockIdx.x * 256 + threadIdx.x;
    if (i < T_ * H_) out[i] = 0.f;
    if (i < E_) g_cnt[i] = 0;
}

// ---------------- kernel 1: router (logits -> top8 -> scatter) ----------------
__global__ void k_router(const float* __restrict__ x, const float* __restrict__ gw) {
    __shared__ float sx[H_];
    __shared__ float slog[E_];
    const int t = blockIdx.x;
    const int tid = threadIdx.x;           // 64 threads, one expert each

    const float4* xr  = (const float4*)(x + (size_t)t * H_);
    float4*       sx4 = (float4*)sx;
    for (int i = tid; i < H_ / 4; i += 64) sx4[i] = xr[i];
    __syncthreads();

    const float4* g4 = (const float4*)(gw + (size_t)tid * H_);
    float acc = 0.f;
    for (int i = 0; i < H_ / 4; i++) {
        float4 a = sx4[i]; float4 b = g4[i];
        acc += a.x * b.x + a.y * b.y + a.z * b.z + a.w * b.w;
    }
    slog[tid] = acc;
    __syncthreads();

    if (tid == 0) {
        int ids[K_]; float lv[K_];
        unsigned long long mask = 0;
        for (int j = 0; j < K_; j++) {
            float best = -1e30f; int bi = 0;
            for (int e = 0; e < E_; e++) {
                if (!((mask >> e) & 1ull) && slog[e] > best) { best = slog[e]; bi = e; }
            }
            mask |= 1ull << bi; ids[j] = bi; lv[j] = best;
        }
        // renormalized top-k of softmax == softmax over top-k logits
        float m = lv[0], s = 0.f, w[K_];
        for (int j = 0; j < K_; j++) { w[j] = __expf(lv[j] - m); s += w[j]; }
        float inv = 1.f / s;
        for (int j = 0; j < K_; j++) {
            int e = ids[j];
            int slot = atomicAdd(&g_cnt[e], 1);
            g_tok[e][slot] = t;
            g_cw [e][slot] = w[j] * inv;
        }
    }
}

// ---------------- kernel 1b: exclusive scan of counts -> slab offsets ----------------
__global__ void k_scan() {
    if (threadIdx.x == 0) {
        int acc = 0;
        for (int e = 0; e < E_; e++) { g_off[e] = acc; acc += g_cnt[e]; }
    }
}

// ---------------- kernel 2: grouped GEMM1 (gate|up fused) + SwiGLU ----------------
// block tile: M=64 tokens x N=128 (64 gate | 64 up), 8 warps each 32x32
__global__ __launch_bounds__(256) void k_gemm1(const float* __restrict__ x,
                                               const float* __restrict__ wg,
                                               const float* __restrict__ wu) {
    const int e  = blockIdx.z;
    const int Ne = g_cnt[e];
    const int m0 = blockIdx.y * 64;
    if (m0 >= Ne) return;
    const int n0 = blockIdx.x * 64;

    __shared__ union {
        struct {
            float Ah[2][64][20];   // 10240 B
            float Al[2][64][20];   // 10240 B
            float B [2][16][136];  // 17408 B
        } p;                       // 37888 B total
        float ep[64][132];         // 33792 B (epilogue alias)
    } sm;

    const int tid  = threadIdx.x;
    const int lane = tid & 31, wid = tid >> 5;
    const int mw = (wid >> 2) * 32;   // 0 / 32
    const int nw = (wid & 3) * 32;    // 0..96

    // A (gathered x rows) load mapping: 1 float4/thread/chunk
    const int arow = tid >> 2;
    const int ak4  = tid & 3;
    const bool avalid = (m0 + arow) < Ne;
    const int tokid = avalid ? g_tok[e][m0 + arow] : 0;
    const float4* xrow = (const float4*)(x + (size_t)tokid * H_);

    // B load mapping: 1 float4/thread/chunk per matrix
    const int bk  = tid >> 4;          // 0..15
    const int bn4 = (tid & 15) * 4;    // 0..60
    const float* wgB = wg + (size_t)e * H_ * F_ + (size_t)bk * F_ + n0 + bn4;
    const float* wuB = wu + (size_t)e * H_ * F_ + (size_t)bk * F_ + n0 + bn4;

    float acc[2][4][4];
#pragma unroll
    for (int mi = 0; mi < 2; mi++)
#pragma unroll
        for (int ni = 0; ni < 4; ni++)
#pragma unroll
            for (int f = 0; f < 4; f++) acc[mi][ni][f] = 0.f;

    float4 rA, rG, rU;
    const float4 f40 = make_float4(0.f, 0.f, 0.f, 0.f);

    auto ld = [&](int kt) {
        rA = avalid ? xrow[kt * (KC / 4) + ak4] : f40;
        rG = *(const float4*)(wgB + (size_t)kt * KC * F_);
        rU = *(const float4*)(wuB + (size_t)kt * KC * F_);
    };
    auto st = [&](int buf) {
        uint4 hi, lo;
        tfsplit(rA.x, hi.x, lo.x); tfsplit(rA.y, hi.y, lo.y);
        tfsplit(rA.z, hi.z, lo.z); tfsplit(rA.w, hi.w, lo.w);
        *(uint4*)&sm.p.Ah[buf][arow][ak4 * 4] = hi;
        *(uint4*)&sm.p.Al[buf][arow][ak4 * 4] = lo;
        uint4 cg = { f2tf(rG.x), f2tf(rG.y), f2tf(rG.z), f2tf(rG.w) };
        *(uint4*)&sm.p.B[buf][bk][bn4] = cg;
        uint4 cu = { f2tf(rU.x), f2tf(rU.y), f2tf(rU.z), f2tf(rU.w) };
        *(uint4*)&sm.p.B[buf][bk][64 + bn4] = cu;
    };
    auto compute = [&](int buf) {
#pragma unroll
        for (int ks = 0; ks < 2; ks++) {
            unsigned ah[2][4], al[2][4], b[4][2];
#pragma unroll
            for (int mi = 0; mi < 2; mi++) {
                int r = mw + mi * 16 + (lane >> 2);
                int c = ks * 8 + (lane & 3);
                ah[mi][0] = __float_as_uint(sm.p.Ah[buf][r    ][c    ]);
                ah[mi][1] = __float_as_uint(sm.p.Ah[buf][r + 8][c    ]);
                ah[mi][2] = __float_as_uint(sm.p.Ah[buf][r    ][c + 4]);
                ah[mi][3] = __float_as_uint(sm.p.Ah[buf][r + 8][c + 4]);
                al[mi][0] = __float_as_uint(sm.p.Al[buf][r    ][c    ]);
                al[mi][1] = __float_as_uint(sm.p.Al[buf][r + 8][c    ]);
                al[mi][2] = __float_as_uint(sm.p.Al[buf][r    ][c + 4]);
                al[mi][3] = __float_as_uint(sm.p.Al[buf][r + 8][c + 4]);
            }
#pragma unroll
            for (int ni = 0; ni < 4; ni++) {
                int cc = nw + ni * 8 + (lane >> 2);
                int rr = ks * 8 + (lane & 3);
                b[ni][0] = __float_as_uint(sm.p.B[buf][rr    ][cc]);
                b[ni][1] = __float_as_uint(sm.p.B[buf][rr + 4][cc]);
            }
#pragma unroll
            for (int mi = 0; mi < 2; mi++)
#pragma unroll
                for (int ni = 0; ni < 4; ni++) {
                    mma_tf32(acc[mi][ni], ah[mi][0], ah[mi][1], ah[mi][2], ah[mi][3],
                             b[ni][0], b[ni][1]);
                    mma_tf32(acc[mi][ni], al[mi][0], al[mi][1], al[mi][2], al[mi][3],
                             b[ni][0], b[ni][1]);
                }
        }
    };

    const int NK = H_ / KC;   // 128
    ld(0); st(0); __syncthreads();
    for (int kt = 0; kt < NK; kt++) {
        const int cur = kt & 1;
        if (kt + 1 < NK) ld(kt + 1);
        compute(cur);
        if (kt + 1 < NK) st(cur ^ 1);
        __syncthreads();
    }

    // epilogue: exchange gate/up via smem, SwiGLU * combine weight -> g_h
#pragma unroll
    for (int mi = 0; mi < 2; mi++)
#pragma unroll
        for (int ni = 0; ni < 4; ni++)
#pragma unroll
            for (int f = 0; f < 4; f++) {
                int r = mw + mi * 16 + (lane >> 2) + ((f >= 2) ? 8 : 0);
                int c = nw + ni * 8 + (lane & 3) * 2 + (f & 1);
                sm.ep[r][c] = acc[mi][ni][f];
            }
    __syncthreads();

    float* hout = g_h + ((size_t)(g_off[e] + m0)) * F_ + n0;
    for (int i = tid; i < 64 * 64; i += 256) {
        int m = i >> 6, n = i & 63;
        if (m0 + m < Ne) {
            float g = sm.ep[m][n], u = sm.ep[m][64 + n];
            float sg = g / (1.f + __expf(-g));
            hout[(size_t)m * F_ + n] = sg * u * g_cw[e][m0 + m];
        }
    }
}

// ---------------- kernel 3: grouped GEMM2 (h @ w_down), atomic combine ----------------
// block tile: M=64 x N=128, K=768
__global__ __launch_bounds__(256) void k_gemm2(const float* __restrict__ wd,
                                               float* __restrict__ out) {
    const int e  = blockIdx.z;
    const int Ne = g_cnt[e];
    const int m0 = blockIdx.y * 64;
    if (m0 >= Ne) return;
    const int n0 = blockIdx.x * 128;

    __shared__ struct {
        float Ah[2][64][20];
        float Al[2][64][20];
        float B [2][16][136];
    } sm;

    const int tid  = threadIdx.x;
    const int lane = tid & 31, wid = tid >> 5;
    const int mw = (wid >> 2) * 32;
    const int nw = (wid & 3) * 32;

    const int arow = tid >> 2;
    const int ak4  = tid & 3;
    const bool avalid = (m0 + arow) < Ne;
    const float4* hrow = (const float4*)(g_h + ((size_t)(g_off[e] + m0 + arow)) * F_);

    const int bk0 = tid >> 5,          bn0 = (tid & 31) * 4;
    const int bk1 = (tid + 256) >> 5,  bn1 = (tid & 31) * 4;
    const float* wdB = wd + (size_t)e * F_ * H_ + n0;

    float acc[2][4][4];
#pragma unroll
    for (int mi = 0; mi < 2; mi++)
#pragma unroll
        for (int ni = 0; ni < 4; ni++)
#pragma unroll
            for (int f = 0; f < 4; f++) acc[mi][ni][f] = 0.f;

    float4 rA, rB0, rB1;
    const float4 f40 = make_float4(0.f, 0.f, 0.f, 0.f);

    auto ld = [&](int kt) {
        rA  = avalid ? hrow[kt * (KC / 4) + ak4] : f40;
        rB0 = *(const float4*)(wdB + (size_t)(kt * KC + bk0) * H_ + bn0);
        rB1 = *(const float4*)(wdB + (size_t)(kt * KC + bk1) * H_ + bn1);
    };
    auto st = [&](int buf) {
        uint4 hi, lo;
        tfsplit(rA.x, hi.x, lo.x); tfsplit(rA.y, hi.y, lo.y);
        tfsplit(rA.z, hi.z, lo.z); tfsplit(rA.w, hi.w, lo.w);
        *(uint4*)&sm.Ah[buf][arow][ak4 * 4] = hi;
        *(uint4*)&sm.Al[buf][arow][ak4 * 4] = lo;
        uint4 c0 = { f2tf(rB0.x), f2tf(rB0.y), f2tf(rB0.z), f2tf(rB0.w) };
        *(uint4*)&sm.B[buf][bk0][bn0] = c0;
        uint4 c1 = { f2tf(rB1.x), f2tf(rB1.y), f2tf(rB1.z), f2tf(rB1.w) };
        *(uint4*)&sm.B[buf][bk1][bn1] = c1;
    };
    auto compute = [&](int buf) {
#pragma unroll
        for (int ks = 0; ks < 2; ks++) {
            unsigned ah[2][4], al[2][4], b[4][2];
#pragma unroll
            for (int mi = 0; mi < 2; mi++) {
                int r = mw + mi * 16 + (lane >> 2);
                int c = ks * 8 + (lane & 3);
                ah[mi][0] = __float_as_uint(sm.Ah[buf][r    ][c    ]);
                ah[mi][1] = __float_as_uint(sm.Ah[buf][r + 8][c    ]);
                ah[mi][2] = __float_as_uint(sm.Ah[buf][r    ][c + 4]);
                ah[mi][3] = __float_as_uint(sm.Ah[buf][r + 8][c + 4]);
                al[mi][0] = __float_as_uint(sm.Al[buf][r    ][c    ]);
                al[mi][1] = __float_as_uint(sm.Al[buf][r + 8][c    ]);
                al[mi][2] = __float_as_uint(sm.Al[buf][r    ][c + 4]);
                al[mi][3] = __float_as_uint(sm.Al[buf][r + 8][c + 4]);
            }
#pragma unroll
            for (int ni = 0; ni < 4; ni++) {
                int cc = nw + ni * 8 + (lane >> 2);
                int rr = ks * 8 + (lane & 3);
                b[ni][0] = __float_as_uint(sm.B[buf][rr    ][cc]);
                b[ni][1] = __float_as_uint(sm.B[buf][rr + 4][cc]);
            }
#pragma unroll
            for (int mi = 0; mi < 2; mi++)
#pragma unroll
                for (int ni = 0; ni < 4; ni++) {
                    mma_tf32(acc[mi][ni], ah[mi][0], ah[mi][1], ah[mi][2], ah[mi][3],
                             b[ni][0], b[ni][1]);
                    mma_tf32(acc[mi][ni], al[mi][0], al[mi][1], al[mi][2], al[mi][3],
                             b[ni][0], b[ni][1]);
                }
        }
    };

    const int NK = F_ / KC;   // 48
    ld(0); st(0); __syncthreads();
    for (int kt = 0; kt < NK; kt++) {
        const int cur = kt & 1;
        if (kt + 1 < NK) ld(kt + 1);
        compute(cur);
        if (kt + 1 < NK) st(cur ^ 1);
        __syncthreads();
    }

    // epilogue: atomic accumulate into out rows (token per M-row)
    int toks[2][2];
#pragma unroll
    for (int mi = 0; mi < 2; mi++)
#pragma unroll
        for (int ro = 0; ro < 2; ro++) {
            int r = m0 + mw + mi * 16 + (lane >> 2) + ro * 8;
            toks[mi][ro] = (r < Ne) ? g_tok[e][r] : -1;
        }
#pragma unroll
    for (int mi = 0; mi < 2; mi++)
#pragma unroll
        for (int ni = 0; ni < 4; ni++)
#pragma unroll
            for (int f = 0; f < 4; f++) {
                int tok = toks[mi][f >> 1];
                if (tok >= 0) {
                    int c = n0 + nw + ni * 8 + (lane & 3) * 2 + (f & 1);
                    atomicAdd(&out[(size_t)tok * H_ + c], acc[mi][ni][f]);
                }
            }
}

// ---------------- launch ----------------
extern "C" void kernel_launch(void* const* d_in, const int* in_sizes, int n_in,
                              void* d_out, int out_size) {
    const float* x     = (const float*)d_in[0];
    const float* gw    = (const float*)d_in[1];
    const float* wgate = (const float*)d_in[2];
    const float* wup   = (const float*)d_in[3];
    const float* wdown = (const float*)d_in[4];
    float* out = (float*)d_out;

    k_zero<<<(T_ * H_ + 255) / 256, 256>>>(out);
    k_router<<<T_, 64>>>(x, gw);
    k_scan<<<1, 32>>>();
    k_gemm1<<<dim3(F_ / 64, T_ / 64, E_), 256>>>(x, wgate, wup);
    k_gemm2<<<dim3(H_ / 128, T_ / 64, E_), 256>>>(wdown, out);
}